// round 7
// baseline (speedup 1.0000x reference)
#include <cuda_runtime.h>
#include <math.h>

#define HEADS   8
#define DHEAD   32
#define HS      48
#define WS      48
#define HWs     (HS * WS)          // 2304
#define WIN     7
#define RAD     3
#define KN      (WIN * WIN)        // 49
#define TILE    16                 // 16x16 pixel tile
#define NTHR    256                // 2 channel-groups x 128 pixel-pair threads
#define HALO    (TILE + 2 * RAD)   // 22
#define HPAD    24                 // padded row stride (words); 2-row offset = 48 = 16 banks
#define CHK     8                  // channels staged per chunk per group
#define HALO_PIX (HALO * HALO)     // 484

__global__ __launch_bounds__(NTHR, 2)
void natten2d_kernel(const float* __restrict__ q,
                     const float* __restrict__ k,
                     const float* __restrict__ v,
                     float* __restrict__ out)
{
    // 2 groups x 8 ch x 22 rows x 24 words x 4B = 33792 B; also aliased as the
    // score/prob staging buffer between passes (49 x 128 x 4B = 25088 B).
    __shared__ float sBuf[2][CHK][HALO][HPAD];

    const int t   = threadIdx.x;
    const int g   = t >> 7;              // channel group: 0 -> ch 0-15, 1 -> ch 16-31
    const int lt  = t & 127;             // pixel-pair thread id within group
    const int tx  = lt & 15;
    const int typ = lt >> 4;             // rows {2typ, 2typ+1}

    const int tileX0 = blockIdx.x * TILE;
    const int tileY0 = blockIdx.y * TILE;
    const size_t base = (size_t)blockIdx.z * DHEAD * HWs;

    const int cBase = g * 16;
    const float* qg = q + base + (size_t)cBase * HWs;
    const float* kg = k + base + (size_t)cBase * HWs;
    const float* vg = v + base + (size_t)cBase * HWs;
    float*       og = out + base + (size_t)cBase * HWs;

    const int x    = tileX0 + tx;
    const int y0   = tileY0 + 2 * typ;
    const int y1   = y0 + 1;
    const int pix0 = y0 * WS + x;
    const int pix1 = pix0 + WS;

    float s0[KN], s1[KN];
    #pragma unroll
    for (int n = 0; n < KN; n++) { s0[n] = 0.0f; s1[n] = 0.0f; }

    // ================= pass 1: partial scores over this group's 16 channels =================
    #pragma unroll 1
    for (int cc = 0; cc < 2; cc++) {
        const float* kcc = kg + (size_t)(cc * CHK) * HWs;

        // ---- halo loader: 484 px over 128 group threads, 8 channels inner (MLP=8) ----
        #pragma unroll
        for (int ps = 0; ps < HALO_PIX; ps += 128) {
            const int p = ps + lt;
            if (p < HALO_PIX) {
                const int hy = p / HALO;
                const int hx = p - hy * HALO;
                const int gy = tileY0 + hy - RAD;
                const int gx = tileX0 + hx - RAD;
                const bool valid = (gy >= 0) & (gy < HS) & (gx >= 0) & (gx < WS);
                const int src = min(max(gy, 0), HS - 1) * WS + min(max(gx, 0), WS - 1);
                #pragma unroll
                for (int c = 0; c < CHK; c++) {
                    float val = __ldg(kcc + c * HWs + src);
                    sBuf[g][c][hy][hx] = valid ? val : 0.0f;
                }
            }
        }

        // prefetch first channel's q while halo loads are in flight
        float qn0 = qg[(cc * CHK) * HWs + pix0];
        float qn1 = qg[(cc * CHK) * HWs + pix1];
        __syncthreads();

        #pragma unroll 1
        for (int c = 0; c < CHK; c++) {
            const float q0 = qn0;
            const float q1 = qn1;
            if (c + 1 < CHK) {
                qn0 = qg[(cc * CHK + c + 1) * HWs + pix0];
                qn1 = qg[(cc * CHK + c + 1) * HWs + pix1];
            }
            const float* kb = &sBuf[g][c][2 * typ][tx];
            float wA[7];
            #pragma unroll
            for (int dx = 0; dx < 7; dx++) wA[dx] = kb[dx];
            #pragma unroll
            for (int dy = 0; dy < 7; dy++) {
                float wB[7];
                const float* wr = kb + (dy + 1) * HPAD;
                #pragma unroll
                for (int dx = 0; dx < 7; dx++) wB[dx] = wr[dx];
                #pragma unroll
                for (int dx = 0; dx < 7; dx++) {
                    s0[dy * 7 + dx] = fmaf(q0, wA[dx], s0[dy * 7 + dx]); // px0: row 2typ+dy
                    s1[dy * 7 + dx] = fmaf(q1, wB[dx], s1[dy * 7 + dx]); // px1: row 2typ+dy+1
                }
                #pragma unroll
                for (int dx = 0; dx < 7; dx++) wA[dx] = wB[dx];
            }
        }
        __syncthreads();  // done reading chunk before overwrite / staging
    }

    // ================= cross-group score reduction + softmax (via smem stage) =================
    float* stage = &sBuf[0][0][0][0];   // 49*128 floats = 25088 B, fits in sBuf

    if (g == 1) {
        #pragma unroll
        for (int n = 0; n < KN; n++) stage[n * 128 + lt] = s0[n];
    }
    __syncthreads();
    if (g == 0) {
        #pragma unroll
        for (int n = 0; n < KN; n++) s0[n] += stage[n * 128 + lt];
    }
    __syncthreads();
    if (g == 1) {
        #pragma unroll
        for (int n = 0; n < KN; n++) stage[n * 128 + lt] = s1[n];
    }
    __syncthreads();
    if (g == 0) {
        #pragma unroll
        for (int n = 0; n < KN; n++) s1[n] += stage[n * 128 + lt];

        // mask + scale + softmax for both pixels (full scores now in s0/s1)
        const float scale = 0.17677669529663687f; // 1/sqrt(32)
        float m0 = -1e30f, m1 = -1e30f;
        #pragma unroll
        for (int n = 0; n < KN; n++) {
            const int dy = n / WIN - RAD;
            const int dx = n % WIN - RAD;
            const int gx = x + dx;
            const bool vx = (gx >= 0) & (gx < WS);
            const int gy0 = y0 + dy;
            const int gy1 = y1 + dy;
            const bool ok0 = vx & (gy0 >= 0) & (gy0 < HS);
            const bool ok1 = vx & (gy1 >= 0) & (gy1 < HS);
            s0[n] = ok0 ? s0[n] * scale : -1e30f;
            s1[n] = ok1 ? s1[n] * scale : -1e30f;
            m0 = fmaxf(m0, s0[n]);
            m1 = fmaxf(m1, s1[n]);
        }
        float sum0 = 0.0f, sum1 = 0.0f;
        #pragma unroll
        for (int n = 0; n < KN; n++) {
            s0[n] = __expf(s0[n] - m0);
            s1[n] = __expf(s1[n] - m1);
            sum0 += s0[n];
            sum1 += s1[n];
        }
        const float inv0 = 1.0f / sum0;
        const float inv1 = 1.0f / sum1;
        #pragma unroll
        for (int n = 0; n < KN; n++) { s0[n] *= inv0; s1[n] *= inv1; }
    }
    __syncthreads();

    // broadcast normalized probs group0 -> group1
    if (g == 0) {
        #pragma unroll
        for (int n = 0; n < KN; n++) stage[n * 128 + lt] = s0[n];
    }
    __syncthreads();
    if (g == 1) {
        #pragma unroll
        for (int n = 0; n < KN; n++) s0[n] = stage[n * 128 + lt];
    }
    __syncthreads();
    if (g == 0) {
        #pragma unroll
        for (int n = 0; n < KN; n++) stage[n * 128 + lt] = s1[n];
    }
    __syncthreads();
    if (g == 1) {
        #pragma unroll
        for (int n = 0; n < KN; n++) s1[n] = stage[n * 128 + lt];
    }
    __syncthreads();  // stage dead before pass-2 loader reuses the buffer

    // ================= pass 2: output for this group's 16 channels =================
    #pragma unroll 1
    for (int cc = 0; cc < 2; cc++) {
        const float* vcc = vg + (size_t)(cc * CHK) * HWs;

        #pragma unroll
        for (int ps = 0; ps < HALO_PIX; ps += 128) {
            const int p = ps + lt;
            if (p < HALO_PIX) {
                const int hy = p / HALO;
                const int hx = p - hy * HALO;
                const int gy = tileY0 + hy - RAD;
                const int gx = tileX0 + hx - RAD;
                const bool valid = (gy >= 0) & (gy < HS) & (gx >= 0) & (gx < WS);
                const int src = min(max(gy, 0), HS - 1) * WS + min(max(gx, 0), WS - 1);
                #pragma unroll
                for (int c = 0; c < CHK; c++) {
                    float val = __ldg(vcc + c * HWs + src);
                    sBuf[g][c][hy][hx] = valid ? val : 0.0f;
                }
            }
        }
        __syncthreads();

        #pragma unroll 1
        for (int c = 0; c < CHK; c++) {
            const float* vb = &sBuf[g][c][2 * typ][tx];
            float a0 = 0.f, a1 = 0.f, a2 = 0.f, a3 = 0.f;   // px0 chains
            float b0 = 0.f, b1 = 0.f, b2 = 0.f, b3 = 0.f;   // px1 chains
            float wA[7];
            #pragma unroll
            for (int dx = 0; dx < 7; dx++) wA[dx] = vb[dx];
            #pragma unroll
            for (int dy = 0; dy < 7; dy++) {
                float wB[7];
                const float* wr = vb + (dy + 1) * HPAD;
                #pragma unroll
                for (int dx = 0; dx < 7; dx++) wB[dx] = wr[dx];
                const int n = dy * 7;
                a0 = fmaf(s0[n + 0], wA[0], a0);
                a1 = fmaf(s0[n + 1], wA[1], a1);
                a2 = fmaf(s0[n + 2], wA[2], a2);
                a3 = fmaf(s0[n + 3], wA[3], a3);
                a0 = fmaf(s0[n + 4], wA[4], a0);
                a1 = fmaf(s0[n + 5], wA[5], a1);
                a2 = fmaf(s0[n + 6], wA[6], a2);
                b0 = fmaf(s1[n + 0], wB[0], b0);
                b1 = fmaf(s1[n + 1], wB[1], b1);
                b2 = fmaf(s1[n + 2], wB[2], b2);
                b3 = fmaf(s1[n + 3], wB[3], b3);
                b0 = fmaf(s1[n + 4], wB[4], b0);
                b1 = fmaf(s1[n + 5], wB[5], b1);
                b2 = fmaf(s1[n + 6], wB[6], b2);
                #pragma unroll
                for (int dx = 0; dx < 7; dx++) wA[dx] = wB[dx];
            }
            og[(cc * CHK + c) * HWs + pix0] = (a0 + a1) + (a2 + a3);
            og[(cc * CHK + c) * HWs + pix1] = (b0 + b1) + (b2 + b3);
        }
        __syncthreads();
    }
}

extern "C" void kernel_launch(void* const* d_in, const int* in_sizes, int n_in,
                              void* d_out, int out_size)
{
    const float* q = (const float*)d_in[0];
    const float* k = (const float*)d_in[1];
    const float* v = (const float*)d_in[2];
    float* o = (float*)d_out;

    const int B = in_sizes[0] / (HEADS * DHEAD * HWs); // 4
    dim3 grid(WS / TILE, HS / TILE, B * HEADS);        // (3, 3, 32) = 288
    dim3 block(NTHR);                                  // 256 linear
    natten2d_kernel<<<grid, block>>>(q, k, v, o);
}